// round 1
// baseline (speedup 1.0000x reference)
#include <cuda_runtime.h>

#define S   128
#define MO  256      // M_OUT
#define RT  8        // rows per block tile
#define NT  256      // threads per block

// Precomputed composed layer-1 vector path: C = Wh1 @ Wu1 @ W1 * (1/sqrt(128))
__device__ float g_T[S * S];
__device__ float g_C[S * MO];

// 4-term fma chain: acc += a.x*w0 + a.y*w1 + a.z*w2 + a.w*w3
#define FMA4(acc, a, w0, w1, w2, w3) \
    (acc) = fmaf((a).x, (w0), fmaf((a).y, (w1), fmaf((a).z, (w2), fmaf((a).w, (w3), (acc)))))

__global__ void prep_T(const float* __restrict__ Wh1, const float* __restrict__ Wu1) {
    int m = blockIdx.x, o = threadIdx.x;
    float acc = 0.f;
#pragma unroll 8
    for (int h = 0; h < S; h++)
        acc = fmaf(__ldg(&Wh1[m * S + h]), __ldg(&Wu1[h * S + o]), acc);
    g_T[m * S + o] = acc;
}

__global__ void prep_C(const float* __restrict__ W1) {
    int m = blockIdx.x, n = threadIdx.x;
    float acc = 0.f;
#pragma unroll 8
    for (int o = 0; o < S; o++)
        acc = fmaf(g_T[m * S + o], __ldg(&W1[o * MO + n]), acc);
    g_C[m * MO + n] = acc * 0.08838834764831845f;  // 1/sqrt(128)
}

__global__ void __launch_bounds__(NT) fused_gvp(
    const float* __restrict__ xin,
    const float* __restrict__ Wh0,
    const float* __restrict__ Wu0,
    const float* __restrict__ Wm0,
    const float* __restrict__ bm0,
    float* __restrict__ out)
{
    // 32 KB static smem
    __shared__ float smemf[8 * RT * S];
    float* vT  = smemf;               // [3][RT][S]  v, later v1 (t-major)
    float* vhT = smemf + 3 * RT * S;  // [3][RT][S]  Vh (t-major)
    float* vnb = smemf + 6 * RT * S;  // [RT][S]     vn
    float* sgb = smemf + 7 * RT * S;  // [RT][S]     s, later gate g

    const int tid  = threadIdx.x;
    const int row0 = blockIdx.x * RT;
    const int c    = tid & (S - 1);   // channel 0..127
    const int rg   = tid >> 7;        // row group 0/1 (4 rows each)

    // ---------------- load tile (8 rows x 512 floats) ----------------
    {
        const float* src = xin + (size_t)row0 * 512;
#pragma unroll
        for (int i = 0; i < (RT * 512) / NT; i++) {
            int idx = i * NT + tid;
            int r = idx >> 9, j = idx & 511;
            float val = src[idx];
            if (j < S) {
                sgb[r * S + j] = val;
            } else {
                int jj = j - S;
                int m = jj / 3;
                int t = jj - 3 * m;
                vT[(t * RT + r) * S + m] = val;
            }
        }
    }
    __syncthreads();

    float acc0[4], acc1[4], acc2[4];

    // ---------------- phase 1: Vh[h][t] = sum_m v[m][t] * Wh0[m][h], vn ----------------
#pragma unroll
    for (int rr = 0; rr < 4; rr++) { acc0[rr] = 0.f; acc1[rr] = 0.f; acc2[rr] = 0.f; }
    for (int m = 0; m < S; m += 4) {
        float w0 = __ldg(&Wh0[(m + 0) * S + c]);
        float w1 = __ldg(&Wh0[(m + 1) * S + c]);
        float w2 = __ldg(&Wh0[(m + 2) * S + c]);
        float w3 = __ldg(&Wh0[(m + 3) * S + c]);
#pragma unroll
        for (int rr = 0; rr < 4; rr++) {
            int r = rg * 4 + rr;
            float4 a = *(const float4*)&vT[(0 * RT + r) * S + m];
            float4 b = *(const float4*)&vT[(1 * RT + r) * S + m];
            float4 d = *(const float4*)&vT[(2 * RT + r) * S + m];
            FMA4(acc0[rr], a, w0, w1, w2, w3);
            FMA4(acc1[rr], b, w0, w1, w2, w3);
            FMA4(acc2[rr], d, w0, w1, w2, w3);
        }
    }
#pragma unroll
    for (int rr = 0; rr < 4; rr++) {
        int r = rg * 4 + rr;
        vhT[(0 * RT + r) * S + c] = acc0[rr];
        vhT[(1 * RT + r) * S + c] = acc1[rr];
        vhT[(2 * RT + r) * S + c] = acc2[rr];
        float n2 = fmaf(acc0[rr], acc0[rr],
                   fmaf(acc1[rr], acc1[rr],
                   fmaf(acc2[rr], acc2[rr], 1e-8f)));
        vnb[r * S + c] = sqrtf(n2);
    }
    __syncthreads();

    // ---------------- phase 2: sm[m] = [s, vn] @ Wm0 + bm0; g = sigmoid(sm) ----------------
    {
        float sacc[4];
        float bb = __ldg(&bm0[c]);
#pragma unroll
        for (int rr = 0; rr < 4; rr++) sacc[rr] = bb;
        for (int k = 0; k < S; k += 4) {
            float w0 = __ldg(&Wm0[(k + 0) * S + c]);
            float w1 = __ldg(&Wm0[(k + 1) * S + c]);
            float w2 = __ldg(&Wm0[(k + 2) * S + c]);
            float w3 = __ldg(&Wm0[(k + 3) * S + c]);
#pragma unroll
            for (int rr = 0; rr < 4; rr++) {
                float4 sv = *(const float4*)&sgb[(rg * 4 + rr) * S + k];
                FMA4(sacc[rr], sv, w0, w1, w2, w3);
            }
        }
        for (int k = 0; k < S; k += 4) {
            float w0 = __ldg(&Wm0[(S + k + 0) * S + c]);
            float w1 = __ldg(&Wm0[(S + k + 1) * S + c]);
            float w2 = __ldg(&Wm0[(S + k + 2) * S + c]);
            float w3 = __ldg(&Wm0[(S + k + 3) * S + c]);
#pragma unroll
            for (int rr = 0; rr < 4; rr++) {
                float4 nv = *(const float4*)&vnb[(rg * 4 + rr) * S + k];
                FMA4(sacc[rr], nv, w0, w1, w2, w3);
            }
        }
        __syncthreads();   // everyone done READING sgb (s) before we overwrite with g
#pragma unroll
        for (int rr = 0; rr < 4; rr++) {
            int r = rg * 4 + rr;
            sgb[r * S + c] = 1.f / (1.f + __expf(-sacc[rr]));
        }
    }
    __syncthreads();

    // ---------------- phase 3: v1[o][t] = g[o] * sum_h Vh[h][t] * Wu0[h][o] ----------------
#pragma unroll
    for (int rr = 0; rr < 4; rr++) { acc0[rr] = 0.f; acc1[rr] = 0.f; acc2[rr] = 0.f; }
    for (int h = 0; h < S; h += 4) {
        float w0 = __ldg(&Wu0[(h + 0) * S + c]);
        float w1 = __ldg(&Wu0[(h + 1) * S + c]);
        float w2 = __ldg(&Wu0[(h + 2) * S + c]);
        float w3 = __ldg(&Wu0[(h + 3) * S + c]);
#pragma unroll
        for (int rr = 0; rr < 4; rr++) {
            int r = rg * 4 + rr;
            float4 a = *(const float4*)&vhT[(0 * RT + r) * S + h];
            float4 b = *(const float4*)&vhT[(1 * RT + r) * S + h];
            float4 d = *(const float4*)&vhT[(2 * RT + r) * S + h];
            FMA4(acc0[rr], a, w0, w1, w2, w3);
            FMA4(acc1[rr], b, w0, w1, w2, w3);
            FMA4(acc2[rr], d, w0, w1, w2, w3);
        }
    }
#pragma unroll
    for (int rr = 0; rr < 4; rr++) {
        int r = rg * 4 + rr;
        float gg = sgb[r * S + c];
        vT[(0 * RT + r) * S + c] = acc0[rr] * gg;
        vT[(1 * RT + r) * S + c] = acc1[rr] * gg;
        vT[(2 * RT + r) * S + c] = acc2[rr] * gg;
    }
    __syncthreads();

    // ---------------- phase 4: vo[n][t] = sum_m v1[m][t] * C[m][n]  (C includes 1/sqrt(S)) ----------------
    {
        const int n = tid;     // 0..255 output channels
        float o0[RT], o1[RT], o2[RT];
#pragma unroll
        for (int r = 0; r < RT; r++) { o0[r] = 0.f; o1[r] = 0.f; o2[r] = 0.f; }
        for (int m = 0; m < S; m += 4) {
            float w0 = __ldg(&g_C[(m + 0) * MO + n]);
            float w1 = __ldg(&g_C[(m + 1) * MO + n]);
            float w2 = __ldg(&g_C[(m + 2) * MO + n]);
            float w3 = __ldg(&g_C[(m + 3) * MO + n]);
#pragma unroll
            for (int r = 0; r < RT; r++) {
                float4 a = *(const float4*)&vT[(0 * RT + r) * S + m];
                float4 b = *(const float4*)&vT[(1 * RT + r) * S + m];
                float4 d = *(const float4*)&vT[(2 * RT + r) * S + m];
                FMA4(o0[r], a, w0, w1, w2, w3);
                FMA4(o1[r], b, w0, w1, w2, w3);
                FMA4(o2[r], d, w0, w1, w2, w3);
            }
        }

        // Output layout per row (1024 f32): [FACTOR=16][64]; j<16 -> scalar (exact 0),
        // j>=16 -> vo[f*16 + (j-16)/3][(j-16)%3]
        const int f  = n >> 4;
        const int nl = n & 15;
#pragma unroll
        for (int r = 0; r < RT; r++) {
            float* orow = out + (size_t)(row0 + r) * 1024 + f * 64;
            orow[nl]              = 0.f;            // antisymmetric scalar channel cancels exactly
            orow[16 + nl * 3 + 0] = o0[r];
            orow[16 + nl * 3 + 1] = o1[r];
            orow[16 + nl * 3 + 2] = o2[r];
        }
    }
}

extern "C" void kernel_launch(void* const* d_in, const int* in_sizes, int n_in,
                              void* d_out, int out_size) {
    const float* x   = (const float*)d_in[0];   // mo_coeffs (2048*16, 512)
    const float* Wh0 = (const float*)d_in[1];
    const float* Wu0 = (const float*)d_in[2];
    const float* Wm0 = (const float*)d_in[3];
    const float* bm0 = (const float*)d_in[4];
    const float* Wh1 = (const float*)d_in[5];
    const float* Wu1 = (const float*)d_in[6];
    // d_in[7] = Wm1, d_in[8] = bm1, d_in[9] = W0 : provably unused (scalar channel cancels)
    const float* W1  = (const float*)d_in[10];
    float* out = (float*)d_out;

    const int rows = in_sizes[0] / 512;          // 32768

    prep_T<<<S, S>>>(Wh1, Wu1);
    prep_C<<<S, MO>>>(W1);
    fused_gvp<<<rows / RT, NT>>>(x, Wh0, Wu0, Wm0, bm0, out);
}

// round 2
// speedup vs baseline: 1.0013x; 1.0013x over previous
#include <cuda_runtime.h>

#define S   128
#define MO  256      // M_OUT
#define RT  8        // rows per block tile
#define NT  256      // threads per block

// Precomputed composed layer-1 vector path: C = Wh1 @ Wu1 @ W1 * (1/sqrt(128))
__device__ float g_T[S * S];
__device__ float g_C[S * MO];

// 4-term fma chain: acc += a.x*w0 + a.y*w1 + a.z*w2 + a.w*w3
#define FMA4(acc, a, w0, w1, w2, w3) \
    (acc) = fmaf((a).x, (w0), fmaf((a).y, (w1), fmaf((a).z, (w2), fmaf((a).w, (w3), (acc)))))

__global__ void prep_T(const float* __restrict__ Wh1, const float* __restrict__ Wu1) {
    int m = blockIdx.x, o = threadIdx.x;
    float acc = 0.f;
#pragma unroll 8
    for (int h = 0; h < S; h++)
        acc = fmaf(__ldg(&Wh1[m * S + h]), __ldg(&Wu1[h * S + o]), acc);
    g_T[m * S + o] = acc;
}

__global__ void prep_C(const float* __restrict__ W1) {
    int m = blockIdx.x, n = threadIdx.x;
    float acc = 0.f;
#pragma unroll 8
    for (int o = 0; o < S; o++)
        acc = fmaf(g_T[m * S + o], __ldg(&W1[o * MO + n]), acc);
    g_C[m * MO + n] = acc * 0.08838834764831845f;  // 1/sqrt(128)
}

__global__ void __launch_bounds__(NT) fused_gvp(
    const float* __restrict__ xin,
    const float* __restrict__ Wh0,
    const float* __restrict__ Wu0,
    const float* __restrict__ Wm0,
    const float* __restrict__ bm0,
    float* __restrict__ out)
{
    // 32 KB static smem
    __shared__ float smemf[8 * RT * S];
    float* vT  = smemf;               // [3][RT][S]  v, later v1 (t-major)
    float* vhT = smemf + 3 * RT * S;  // [3][RT][S]  Vh (t-major)
    float* vnb = smemf + 6 * RT * S;  // [RT][S]     vn
    float* sgb = smemf + 7 * RT * S;  // [RT][S]     s, later gate g

    const int tid  = threadIdx.x;
    const int row0 = blockIdx.x * RT;
    const int c    = tid & (S - 1);   // channel 0..127
    const int rg   = tid >> 7;        // row group 0/1 (4 rows each)

    // ---------------- load tile (8 rows x 512 floats) ----------------
    {
        const float* src = xin + (size_t)row0 * 512;
#pragma unroll
        for (int i = 0; i < (RT * 512) / NT; i++) {
            int idx = i * NT + tid;
            int r = idx >> 9, j = idx & 511;
            float val = src[idx];
            if (j < S) {
                sgb[r * S + j] = val;
            } else {
                int jj = j - S;
                int m = jj / 3;
                int t = jj - 3 * m;
                vT[(t * RT + r) * S + m] = val;
            }
        }
    }
    __syncthreads();

    float acc0[4], acc1[4], acc2[4];

    // ---------------- phase 1: Vh[h][t] = sum_m v[m][t] * Wh0[m][h], vn ----------------
#pragma unroll
    for (int rr = 0; rr < 4; rr++) { acc0[rr] = 0.f; acc1[rr] = 0.f; acc2[rr] = 0.f; }
    for (int m = 0; m < S; m += 4) {
        float w0 = __ldg(&Wh0[(m + 0) * S + c]);
        float w1 = __ldg(&Wh0[(m + 1) * S + c]);
        float w2 = __ldg(&Wh0[(m + 2) * S + c]);
        float w3 = __ldg(&Wh0[(m + 3) * S + c]);
#pragma unroll
        for (int rr = 0; rr < 4; rr++) {
            int r = rg * 4 + rr;
            float4 a = *(const float4*)&vT[(0 * RT + r) * S + m];
            float4 b = *(const float4*)&vT[(1 * RT + r) * S + m];
            float4 d = *(const float4*)&vT[(2 * RT + r) * S + m];
            FMA4(acc0[rr], a, w0, w1, w2, w3);
            FMA4(acc1[rr], b, w0, w1, w2, w3);
            FMA4(acc2[rr], d, w0, w1, w2, w3);
        }
    }
#pragma unroll
    for (int rr = 0; rr < 4; rr++) {
        int r = rg * 4 + rr;
        vhT[(0 * RT + r) * S + c] = acc0[rr];
        vhT[(1 * RT + r) * S + c] = acc1[rr];
        vhT[(2 * RT + r) * S + c] = acc2[rr];
        float n2 = fmaf(acc0[rr], acc0[rr],
                   fmaf(acc1[rr], acc1[rr],
                   fmaf(acc2[rr], acc2[rr], 1e-8f)));
        vnb[r * S + c] = sqrtf(n2);
    }
    __syncthreads();

    // ---------------- phase 2: sm[m] = [s, vn] @ Wm0 + bm0; g = sigmoid(sm) ----------------
    {
        float sacc[4];
        float bb = __ldg(&bm0[c]);
#pragma unroll
        for (int rr = 0; rr < 4; rr++) sacc[rr] = bb;
        for (int k = 0; k < S; k += 4) {
            float w0 = __ldg(&Wm0[(k + 0) * S + c]);
            float w1 = __ldg(&Wm0[(k + 1) * S + c]);
            float w2 = __ldg(&Wm0[(k + 2) * S + c]);
            float w3 = __ldg(&Wm0[(k + 3) * S + c]);
#pragma unroll
            for (int rr = 0; rr < 4; rr++) {
                float4 sv = *(const float4*)&sgb[(rg * 4 + rr) * S + k];
                FMA4(sacc[rr], sv, w0, w1, w2, w3);
            }
        }
        for (int k = 0; k < S; k += 4) {
            float w0 = __ldg(&Wm0[(S + k + 0) * S + c]);
            float w1 = __ldg(&Wm0[(S + k + 1) * S + c]);
            float w2 = __ldg(&Wm0[(S + k + 2) * S + c]);
            float w3 = __ldg(&Wm0[(S + k + 3) * S + c]);
#pragma unroll
            for (int rr = 0; rr < 4; rr++) {
                float4 nv = *(const float4*)&vnb[(rg * 4 + rr) * S + k];
                FMA4(sacc[rr], nv, w0, w1, w2, w3);
            }
        }
        __syncthreads();   // everyone done READING sgb (s) before we overwrite with g
#pragma unroll
        for (int rr = 0; rr < 4; rr++) {
            int r = rg * 4 + rr;
            sgb[r * S + c] = 1.f / (1.f + __expf(-sacc[rr]));
        }
    }
    __syncthreads();

    // ---------------- phase 3: v1[o][t] = g[o] * sum_h Vh[h][t] * Wu0[h][o] ----------------
#pragma unroll
    for (int rr = 0; rr < 4; rr++) { acc0[rr] = 0.f; acc1[rr] = 0.f; acc2[rr] = 0.f; }
    for (int h = 0; h < S; h += 4) {
        float w0 = __ldg(&Wu0[(h + 0) * S + c]);
        float w1 = __ldg(&Wu0[(h + 1) * S + c]);
        float w2 = __ldg(&Wu0[(h + 2) * S + c]);
        float w3 = __ldg(&Wu0[(h + 3) * S + c]);
#pragma unroll
        for (int rr = 0; rr < 4; rr++) {
            int r = rg * 4 + rr;
            float4 a = *(const float4*)&vhT[(0 * RT + r) * S + h];
            float4 b = *(const float4*)&vhT[(1 * RT + r) * S + h];
            float4 d = *(const float4*)&vhT[(2 * RT + r) * S + h];
            FMA4(acc0[rr], a, w0, w1, w2, w3);
            FMA4(acc1[rr], b, w0, w1, w2, w3);
            FMA4(acc2[rr], d, w0, w1, w2, w3);
        }
    }
#pragma unroll
    for (int rr = 0; rr < 4; rr++) {
        int r = rg * 4 + rr;
        float gg = sgb[r * S + c];
        vT[(0 * RT + r) * S + c] = acc0[rr] * gg;
        vT[(1 * RT + r) * S + c] = acc1[rr] * gg;
        vT[(2 * RT + r) * S + c] = acc2[rr] * gg;
    }
    __syncthreads();

    // ---------------- phase 4: vo[n][t] = sum_m v1[m][t] * C[m][n]  (C includes 1/sqrt(S)) ----------------
    {
        const int n = tid;     // 0..255 output channels
        float o0[RT], o1[RT], o2[RT];
#pragma unroll
        for (int r = 0; r < RT; r++) { o0[r] = 0.f; o1[r] = 0.f; o2[r] = 0.f; }
        for (int m = 0; m < S; m += 4) {
            float w0 = __ldg(&g_C[(m + 0) * MO + n]);
            float w1 = __ldg(&g_C[(m + 1) * MO + n]);
            float w2 = __ldg(&g_C[(m + 2) * MO + n]);
            float w3 = __ldg(&g_C[(m + 3) * MO + n]);
#pragma unroll
            for (int r = 0; r < RT; r++) {
                float4 a = *(const float4*)&vT[(0 * RT + r) * S + m];
                float4 b = *(const float4*)&vT[(1 * RT + r) * S + m];
                float4 d = *(const float4*)&vT[(2 * RT + r) * S + m];
                FMA4(o0[r], a, w0, w1, w2, w3);
                FMA4(o1[r], b, w0, w1, w2, w3);
                FMA4(o2[r], d, w0, w1, w2, w3);
            }
        }

        // Output layout per row (1024 f32): [FACTOR=16][64]; j<16 -> scalar (exact 0),
        // j>=16 -> vo[f*16 + (j-16)/3][(j-16)%3]
        const int f  = n >> 4;
        const int nl = n & 15;
#pragma unroll
        for (int r = 0; r < RT; r++) {
            float* orow = out + (size_t)(row0 + r) * 1024 + f * 64;
            orow[nl]              = 0.f;            // antisymmetric scalar channel cancels exactly
            orow[16 + nl * 3 + 0] = o0[r];
            orow[16 + nl * 3 + 1] = o1[r];
            orow[16 + nl * 3 + 2] = o2[r];
        }
    }
}

extern "C" void kernel_launch(void* const* d_in, const int* in_sizes, int n_in,
                              void* d_out, int out_size) {
    const float* x   = (const float*)d_in[0];   // mo_coeffs (2048*16, 512)
    const float* Wh0 = (const float*)d_in[1];
    const float* Wu0 = (const float*)d_in[2];
    const float* Wm0 = (const float*)d_in[3];
    const float* bm0 = (const float*)d_in[4];
    const float* Wh1 = (const float*)d_in[5];
    const float* Wu1 = (const float*)d_in[6];
    // d_in[7] = Wm1, d_in[8] = bm1, d_in[9] = W0 : provably unused (scalar channel cancels)
    const float* W1  = (const float*)d_in[10];
    float* out = (float*)d_out;

    const int rows = in_sizes[0] / 512;          // 32768

    prep_T<<<S, S>>>(Wh1, Wu1);
    prep_C<<<S, MO>>>(W1);
    fused_gvp<<<rows / RT, NT>>>(x, Wh0, Wu0, Wm0, bm0, out);
}

// round 4
// speedup vs baseline: 1.7267x; 1.7245x over previous
#include <cuda_runtime.h>
#include <cuda_bf16.h>
#include <stdint.h>

#define S        128
#define MO       256
#define NROWS    32768       // 2048*16
#define XR       64          // x-rows per CTA
#define NTHREADS 384         // 12 warps

// ---------------- smem layout (bytes) ----------------
// A tile: 192 rows x 128 bf16 (256B/row, swizzled), hi+lo   -> 96 KB
// B tile: 128 rows x 128 bf16, hi+lo                        -> 64 KB
// S tile: 64 x 128 bf16 hi+lo (later g fp32 64x128)         -> 32 KB
// VN tile: 64 x 128 bf16 hi+lo (later output staging)       -> 32 KB
#define OFF_A_HI  0
#define OFF_A_LO  49152
#define OFF_B_HI  98304
#define OFF_B_LO  131072
#define OFF_S_HI  163840
#define OFF_S_LO  180224
#define OFF_G     163840
#define OFF_VN_HI 196608
#define OFF_VN_LO 212992
#define OFF_STAGE 196608
#define SMEM_BYTES 229376

// ---------------- weight scratch (tiny) ----------------
__device__ float g_T[S * S];
__device__ float g_C[S * MO];
__device__ __nv_bfloat16 gWhT_hi[S * S],     gWhT_lo[S * S];      // [n][k]
__device__ __nv_bfloat16 gWuT_hi[S * S],     gWuT_lo[S * S];
__device__ __nv_bfloat16 gWmT_hi[2 * S * S], gWmT_lo[2 * S * S];  // [half][n][k]
__device__ __nv_bfloat16 gCT_hi[MO * S],     gCT_lo[MO * S];      // [n][k]

// ---------------- helpers ----------------
// XOR swizzle on 16B chunks within a 256B row: conflict-free ldmatrix
__device__ __forceinline__ uint32_t swoff(int row, int kbyte) {
    return (uint32_t)(row * 256 + ((((kbyte >> 4) ^ (row & 7)) << 4) | (kbyte & 15)));
}

__device__ __forceinline__ void ldsm4(uint32_t* r, uint32_t addr) {
    asm volatile("ldmatrix.sync.aligned.m8n8.x4.shared.b16 {%0,%1,%2,%3}, [%4];"
                 : "=r"(r[0]), "=r"(r[1]), "=r"(r[2]), "=r"(r[3]) : "r"(addr));
}

__device__ __forceinline__ void mma16816(float (&d)[4], const uint32_t* a, const uint32_t* b) {
    asm volatile(
        "mma.sync.aligned.m16n8k16.row.col.f32.bf16.bf16.f32 "
        "{%0,%1,%2,%3},{%4,%5,%6,%7},{%8,%9},{%0,%1,%2,%3};"
        : "+f"(d[0]), "+f"(d[1]), "+f"(d[2]), "+f"(d[3])
        : "r"(a[0]), "r"(a[1]), "r"(a[2]), "r"(a[3]), "r"(b[0]), "r"(b[1]));
}

__device__ __forceinline__ uint32_t pack_bf2(__nv_bfloat16 a, __nv_bfloat16 b) {
    return (uint32_t)__bfloat16_as_ushort(a) | ((uint32_t)__bfloat16_as_ushort(b) << 16);
}
__device__ __forceinline__ float2 unpack_bf2(uint32_t u) {
    __nv_bfloat162 b = *reinterpret_cast<__nv_bfloat162*>(&u);
    return make_float2(__bfloat162float(b.x), __bfloat162float(b.y));
}
__device__ __forceinline__ void split2(float a, float b, uint32_t& hi, uint32_t& lo) {
    __nv_bfloat16 ah = __float2bfloat16(a), bh = __float2bfloat16(b);
    __nv_bfloat16 al = __float2bfloat16(a - __bfloat162float(ah));
    __nv_bfloat16 bl = __float2bfloat16(b - __bfloat162float(bh));
    hi = pack_bf2(ah, bh);
    lo = pack_bf2(al, bl);
}

// split-bf16 GEMM: warp strip of 16 rows x 128 cols, K=128. acc[ntile][4].
__device__ __forceinline__ void gemm_strip(char* smem, uint32_t smu,
                                           uint32_t offA_hi, uint32_t offA_lo,
                                           int rbase, int lane, float (&acc)[16][4],
                                           bool zero_init) {
    if (zero_init) {
#pragma unroll
        for (int i = 0; i < 16; i++)
#pragma unroll
            for (int j = 0; j < 4; j++) acc[i][j] = 0.f;
    }
    const int arow   = rbase + (lane & 15);
    const int akoff  = (lane >> 4) * 16;
    const int bn_off = ((lane >> 4) << 3) + (lane & 7);
    const int bkoff  = ((lane >> 3) & 1) * 16;
#pragma unroll
    for (int kc = 0; kc < 8; kc++) {
        uint32_t ah[4], al[4];
        ldsm4(ah, smu + offA_hi + swoff(arow, kc * 32 + akoff));
        ldsm4(al, smu + offA_lo + swoff(arow, kc * 32 + akoff));
#pragma unroll
        for (int jp = 0; jp < 8; jp++) {
            int n = jp * 16 + bn_off;
            uint32_t bh[4], bl[4];
            ldsm4(bh, smu + OFF_B_HI + swoff(n, kc * 32 + bkoff));
            ldsm4(bl, smu + OFF_B_LO + swoff(n, kc * 32 + bkoff));
            mma16816(acc[2 * jp],     ah, &bh[0]);
            mma16816(acc[2 * jp],     ah, &bl[0]);
            mma16816(acc[2 * jp],     al, &bh[0]);
            mma16816(acc[2 * jp + 1], ah, &bh[2]);
            mma16816(acc[2 * jp + 1], ah, &bl[2]);
            mma16816(acc[2 * jp + 1], al, &bh[2]);
        }
    }
}

// gate GEMM: warp strip 16 rows x 64 cols, K=128, accumulate (no init)
__device__ __forceinline__ void gate_strip(char* smem, uint32_t smu,
                                           uint32_t offA_hi, uint32_t offA_lo,
                                           int rbase, int nbase, int lane,
                                           float (&acc)[8][4]) {
    const int arow   = rbase + (lane & 15);
    const int akoff  = (lane >> 4) * 16;
    const int bn_off = ((lane >> 4) << 3) + (lane & 7);
    const int bkoff  = ((lane >> 3) & 1) * 16;
#pragma unroll
    for (int kc = 0; kc < 8; kc++) {
        uint32_t ah[4], al[4];
        ldsm4(ah, smu + offA_hi + swoff(arow, kc * 32 + akoff));
        ldsm4(al, smu + offA_lo + swoff(arow, kc * 32 + akoff));
#pragma unroll
        for (int jp = 0; jp < 4; jp++) {
            int n = nbase + jp * 16 + bn_off;
            uint32_t bh[4], bl[4];
            ldsm4(bh, smu + OFF_B_HI + swoff(n, kc * 32 + bkoff));
            ldsm4(bl, smu + OFF_B_LO + swoff(n, kc * 32 + bkoff));
            mma16816(acc[2 * jp],     ah, &bh[0]);
            mma16816(acc[2 * jp],     ah, &bl[0]);
            mma16816(acc[2 * jp],     al, &bh[0]);
            mma16816(acc[2 * jp + 1], ah, &bh[2]);
            mma16816(acc[2 * jp + 1], ah, &bl[2]);
            mma16816(acc[2 * jp + 1], al, &bh[2]);
        }
    }
}

__device__ __forceinline__ void load_B(char* smem,
                                       const __nv_bfloat16* __restrict__ gh,
                                       const __nv_bfloat16* __restrict__ gl, int tid) {
    for (int i = tid; i < 2048; i += NTHREADS) {
        int r = i >> 4, c = i & 15;
        uint32_t d = r * 256 + (((c ^ (r & 7))) << 4);
        *(uint4*)(smem + OFF_B_HI + d) = *(const uint4*)(gh + r * 128 + c * 8);
        *(uint4*)(smem + OFF_B_LO + d) = *(const uint4*)(gl + r * 128 + c * 8);
    }
}

// ---------------- weight prep (tiny kernels) ----------------
__global__ void prep_T(const float* __restrict__ Wh1, const float* __restrict__ Wu1) {
    int m = blockIdx.x, o = threadIdx.x;
    float acc = 0.f;
#pragma unroll 8
    for (int h = 0; h < S; h++)
        acc = fmaf(__ldg(&Wh1[m * S + h]), __ldg(&Wu1[h * S + o]), acc);
    g_T[m * S + o] = acc;
}

__global__ void prep_C(const float* __restrict__ W1) {
    int m = blockIdx.x, n = threadIdx.x;
    float acc = 0.f;
#pragma unroll 8
    for (int o = 0; o < S; o++)
        acc = fmaf(g_T[m * S + o], __ldg(&W1[o * MO + n]), acc);
    g_C[m * MO + n] = acc * 0.08838834764831845f;  // 1/sqrt(128)
}

__global__ void pack_w(const float* __restrict__ Wh0, const float* __restrict__ Wu0,
                       const float* __restrict__ Wm0) {
    int i = blockIdx.x * 256 + threadIdx.x;   // 98304 total
    float v;
    __nv_bfloat16 *dh, *dl;
    int pos;
    if (i < 16384) {                       // WhT[n][k] = Wh0[k][n]
        int n = i >> 7, k = i & 127;
        v = Wh0[k * S + n]; dh = gWhT_hi; dl = gWhT_lo; pos = i;
    } else if (i < 32768) {
        int j = i - 16384; int n = j >> 7, k = j & 127;
        v = Wu0[k * S + n]; dh = gWuT_hi; dl = gWuT_lo; pos = j;
    } else if (i < 65536) {                // WmT[half][n][k] = Wm0[half*128+k][n]
        int j = i - 32768; int half = j >> 14, n = (j >> 7) & 127, k = j & 127;
        v = Wm0[(half * S + k) * S + n]; dh = gWmT_hi; dl = gWmT_lo; pos = j;
    } else {                               // CT[n][k] = C[k][n]
        int j = i - 65536; int n = j >> 7, k = j & 127;
        v = g_C[k * MO + n]; dh = gCT_hi; dl = gCT_lo; pos = j;
    }
    __nv_bfloat16 h = __float2bfloat16(v);
    dh[pos] = h;
    dl[pos] = __float2bfloat16(v - __bfloat162float(h));
}

// ---------------- the fused kernel ----------------
__global__ void __launch_bounds__(NTHREADS, 1) fused(
    const float* __restrict__ x,
    const float* __restrict__ bm0,
    float* __restrict__ out)
{
    extern __shared__ char smem[];
    const uint32_t smu = (uint32_t)__cvta_generic_to_shared(smem);
    const int tid  = threadIdx.x;
    const int wid  = tid >> 5;
    const int lane = tid & 31;
    const int row0 = blockIdx.x * XR;
    float* gptr = (float*)(smem + OFF_G);
    float* stg  = (float*)(smem + OFF_STAGE);

    // ===== phase 0: pack input -> S tile + A tile (v, t-major rows t*64+xr) =====
    for (int p = tid; p < XR * 64; p += NTHREADS) {                // s pairs
        int row = p >> 6, c2 = (p & 63) << 1;
        const float* src = x + (size_t)(row0 + row) * 512 + c2;
        uint32_t hi, lo; split2(src[0], src[1], hi, lo);
        uint32_t d = swoff(row, c2 * 2);
        *(uint32_t*)(smem + OFF_S_HI + d) = hi;
        *(uint32_t*)(smem + OFF_S_LO + d) = lo;
    }
    for (int q = tid; q < XR * 384; q += NTHREADS) {               // v scalars
        int xr = q / 384;
        int j  = q - xr * 384;
        int m  = (j * 21846) >> 16;      // j/3
        int t  = j - 3 * m;
        float val = x[(size_t)(row0 + xr) * 512 + 128 + j];
        int row = t * 64 + xr;
        __nv_bfloat16 h = __float2bfloat16(val);
        __nv_bfloat16 l = __float2bfloat16(val - __bfloat162float(h));
        uint32_t d = swoff(row, m * 2);
        *(uint16_t*)(smem + OFF_A_HI + d) = __bfloat16_as_ushort(h);
        *(uint16_t*)(smem + OFF_A_LO + d) = __bfloat16_as_ushort(l);
    }
    load_B(smem, gWhT_hi, gWhT_lo, tid);
    __syncthreads();

    float acc[16][4];
    const int rbase = wid * 16;
    const int r0 = rbase + (lane >> 2), r1 = r0 + 8;
    const int xr0 = r0 & 63, xr1 = r1 & 63;
    const int tcomp = wid >> 2;          // t of this warp's strip

    // ===== phase 1: Vh = v @ Wh0 =====
    gemm_strip(smem, smu, OFF_A_HI, OFF_A_LO, rbase, lane, acc, true);
    __syncthreads();                      // all reads of A (v) and B done
    // store Vh (split) over A
#pragma unroll
    for (int i = 0; i < 16; i++) {
        int c = i * 8 + (lane & 3) * 2;
        uint32_t hi, lo;
        split2(acc[i][0], acc[i][1], hi, lo);
        uint32_t d0 = swoff(r0, c * 2);
        *(uint32_t*)(smem + OFF_A_HI + d0) = hi;
        *(uint32_t*)(smem + OFF_A_LO + d0) = lo;
        split2(acc[i][2], acc[i][3], hi, lo);
        uint32_t d1 = swoff(r1, c * 2);
        *(uint32_t*)(smem + OFF_A_HI + d1) = hi;
        *(uint32_t*)(smem + OFF_A_LO + d1) = lo;
    }
    load_B(smem, gWmT_hi, gWmT_lo, tid);   // Wm half 0
    __syncthreads();

    // ===== phase 2: vn = sqrt(sum_t Vh^2 + eps) =====
    for (int p = tid; p < XR * 64; p += NTHREADS) {
        int xr = p >> 6, h2 = (p & 63) << 1;
        float s0 = 1e-8f, s1 = 1e-8f;
#pragma unroll
        for (int t = 0; t < 3; t++) {
            uint32_t d = swoff(t * 64 + xr, h2 * 2);
            float2 fh = unpack_bf2(*(uint32_t*)(smem + OFF_A_HI + d));
            float2 fl = unpack_bf2(*(uint32_t*)(smem + OFF_A_LO + d));
            float x0 = fh.x + fl.x, x1 = fh.y + fl.y;
            s0 = fmaf(x0, x0, s0);
            s1 = fmaf(x1, x1, s1);
        }
        uint32_t hi, lo; split2(sqrtf(s0), sqrtf(s1), hi, lo);
        uint32_t d = swoff(xr, h2 * 2);
        *(uint32_t*)(smem + OFF_VN_HI + d) = hi;
        *(uint32_t*)(smem + OFF_VN_LO + d) = lo;
    }
    __syncthreads();

    // ===== phase 3: gate = sigmoid([s,vn] @ Wm0 + bm0)  (warps 0-7) =====
    float acc2[8][4];
#pragma unroll
    for (int i = 0; i < 8; i++)
#pragma unroll
        for (int j = 0; j < 4; j++) acc2[i][j] = 0.f;
    const int grb = (wid & 3) * 16;
    const int gnb = (wid >> 2) * 64;
    if (wid < 8)
        gate_strip(smem, smu, OFF_S_HI, OFF_S_LO, grb, gnb, lane, acc2);
    __syncthreads();
    load_B(smem, gWmT_hi + 16384, gWmT_lo + 16384, tid);   // Wm half 1
    __syncthreads();
    if (wid < 8)
        gate_strip(smem, smu, OFF_VN_HI, OFF_VN_LO, grb, gnb, lane, acc2);
    __syncthreads();                      // s reads done -> can overwrite with g
    if (wid < 8) {
        int gr0 = grb + (lane >> 2), gr1 = gr0 + 8;
#pragma unroll
        for (int i = 0; i < 8; i++) {
            int n = gnb + i * 8 + (lane & 3) * 2;
            float b0 = __ldg(&bm0[n]), b1 = __ldg(&bm0[n + 1]);
            gptr[gr0 * 128 + n]     = 1.f / (1.f + __expf(-(acc2[i][0] + b0)));
            gptr[gr0 * 128 + n + 1] = 1.f / (1.f + __expf(-(acc2[i][1] + b1)));
            gptr[gr1 * 128 + n]     = 1.f / (1.f + __expf(-(acc2[i][2] + b0)));
            gptr[gr1 * 128 + n + 1] = 1.f / (1.f + __expf(-(acc2[i][3] + b1)));
        }
    }
    load_B(smem, gWuT_hi, gWuT_lo, tid);
    __syncthreads();

    // ===== phase 4: v1 = (Vh @ Wu0) * g =====
    gemm_strip(smem, smu, OFF_A_HI, OFF_A_LO, rbase, lane, acc, true);
    __syncthreads();                      // Vh reads done
#pragma unroll
    for (int i = 0; i < 16; i++) {
        int c = i * 8 + (lane & 3) * 2;
        float g00 = gptr[xr0 * 128 + c], g01 = gptr[xr0 * 128 + c + 1];
        float g10 = gptr[xr1 * 128 + c], g11 = gptr[xr1 * 128 + c + 1];
        uint32_t hi, lo;
        split2(acc[i][0] * g00, acc[i][1] * g01, hi, lo);
        uint32_t d0 = swoff(r0, c * 2);
        *(uint32_t*)(smem + OFF_A_HI + d0) = hi;
        *(uint32_t*)(smem + OFF_A_LO + d0) = lo;
        split2(acc[i][2] * g10, acc[i][3] * g11, hi, lo);
        uint32_t d1 = swoff(r1, c * 2);
        *(uint32_t*)(smem + OFF_A_HI + d1) = hi;
        *(uint32_t*)(smem + OFF_A_LO + d1) = lo;
    }
    load_B(smem, gCT_hi, gCT_lo, tid);     // C half 0
    __syncthreads();

    // ===== phase 5: vo = v1 @ C (two N-halves), staged coalesced output =====
#pragma unroll 1
    for (int nh = 0; nh < 2; nh++) {
        gemm_strip(smem, smu, OFF_A_HI, OFF_A_LO, rbase, lane, acc, true);
#pragma unroll 1
        for (int slice = 0; slice < 4; slice++) {
            __syncthreads();              // staging free
#pragma unroll
            for (int i = 0; i < 16; i++) {
                int n  = i * 8 + (lane & 3) * 2;
                int fl = n >> 4, nl = n & 15;
                if ((xr0 >> 4) == slice) {
                    stg[(xr0 & 15) * 512 + fl * 64 + 16 + nl * 3 + tcomp]       = acc[i][0];
                    stg[(xr0 & 15) * 512 + fl * 64 + 16 + (nl + 1) * 3 + tcomp] = acc[i][1];
                }
                if ((xr1 >> 4) == slice) {
                    stg[(xr1 & 15) * 512 + fl * 64 + 16 + nl * 3 + tcomp]       = acc[i][2];
                    stg[(xr1 & 15) * 512 + fl * 64 + 16 + (nl + 1) * 3 + tcomp] = acc[i][3];
                }
            }
            __syncthreads();
            for (int i = tid; i < 2048; i += NTHREADS) {
                int xl = i >> 7, posq = (i & 127) << 2;
                float4 v;
                if ((posq & 63) < 16) v = make_float4(0.f, 0.f, 0.f, 0.f);  // scalar: exact cancel
                else                  v = *(float4*)&stg[xl * 512 + posq];
                *(float4*)&out[(size_t)(row0 + slice * 16 + xl) * 1024 + nh * 512 + posq] = v;
            }
        }
        if (nh == 0) {
            __syncthreads();
            load_B(smem, gCT_hi + 128 * 128, gCT_lo + 128 * 128, tid);  // C half 1
            __syncthreads();
        }
    }
}

// ---------------- launch ----------------
extern "C" void kernel_launch(void* const* d_in, const int* in_sizes, int n_in,
                              void* d_out, int out_size) {
    const float* x   = (const float*)d_in[0];
    const float* Wh0 = (const float*)d_in[1];
    const float* Wu0 = (const float*)d_in[2];
    const float* Wm0 = (const float*)d_in[3];
    const float* bm0 = (const float*)d_in[4];
    const float* Wh1 = (const float*)d_in[5];
    const float* Wu1 = (const float*)d_in[6];
    // d_in[7]=Wm1, d_in[8]=bm1, d_in[9]=W0 provably unused (scalar channel cancels)
    const float* W1  = (const float*)d_in[10];
    float* out = (float*)d_out;

    cudaFuncSetAttribute(fused, cudaFuncAttributeMaxDynamicSharedMemorySize, SMEM_BYTES);

    prep_T<<<S, S>>>(Wh1, Wu1);
    prep_C<<<S, MO>>>(W1);
    pack_w<<<384, 256>>>(Wh0, Wu0, Wm0);
    fused<<<NROWS / XR, NTHREADS, SMEM_BYTES>>>(x, bm0, out);
}

// round 5
// speedup vs baseline: 2.3486x; 1.3601x over previous
#include <cuda_runtime.h>
#include <cuda_bf16.h>
#include <stdint.h>

#define S        128
#define MO       256
#define NROWS    32768       // 2048*16
#define XR       64          // x-rows per CTA
#define NTHREADS 768         // 24 warps

// ---------------- smem layout (bytes) ----------------
#define OFF_A_HI  0          // A: 192 rows x 256B (swizzled), hi
#define OFF_A_LO  49152
#define OFF_B_HI  98304      // B: 128 rows x 256B, hi
#define OFF_B_LO  131072
#define OFF_S_HI  163840     // s tile 64x256B hi
#define OFF_S_LO  180224
#define OFF_G     163840     // gate fp32 64x128 (overlaps S after s consumed)
#define OFF_VN_HI 196608     // vn tile hi
#define OFF_VN_LO 212992
#define OFF_STAGE 196608     // output staging 16x512 f32 (overlaps VN)
#define SMEM_BYTES 229376

// ---------------- weight scratch ----------------
__device__ float g_T[S * S];
__device__ float g_C[S * MO];
__device__ __nv_bfloat16 gWhT_hi[S * S],     gWhT_lo[S * S];      // [n][k]
__device__ __nv_bfloat16 gWuT_hi[S * S],     gWuT_lo[S * S];
__device__ __nv_bfloat16 gWmT_hi[2 * S * S], gWmT_lo[2 * S * S];  // [half][n][k]
__device__ __nv_bfloat16 gCT_hi[MO * S],     gCT_lo[MO * S];      // [n][k]

// ---------------- helpers ----------------
__device__ __forceinline__ uint32_t swoff(int row, int kbyte) {
    return (uint32_t)(row * 256 + ((((kbyte >> 4) ^ (row & 7)) << 4) | (kbyte & 15)));
}
// gate buffer: conflict-free row swizzle (xor multiple-of-4 keeps col pairs)
__device__ __forceinline__ uint32_t gswz(int r, int c) {
    return (uint32_t)(r * 128 + (c ^ ((r & 7) << 2)));
}

__device__ __forceinline__ void ldsm4(uint32_t* r, uint32_t addr) {
    asm volatile("ldmatrix.sync.aligned.m8n8.x4.shared.b16 {%0,%1,%2,%3}, [%4];"
                 : "=r"(r[0]), "=r"(r[1]), "=r"(r[2]), "=r"(r[3]) : "r"(addr));
}

__device__ __forceinline__ void mma16816(float (&d)[4], const uint32_t* a, const uint32_t* b) {
    asm volatile(
        "mma.sync.aligned.m16n8k16.row.col.f32.bf16.bf16.f32 "
        "{%0,%1,%2,%3},{%4,%5,%6,%7},{%8,%9},{%0,%1,%2,%3};"
        : "+f"(d[0]), "+f"(d[1]), "+f"(d[2]), "+f"(d[3])
        : "r"(a[0]), "r"(a[1]), "r"(a[2]), "r"(a[3]), "r"(b[0]), "r"(b[1]));
}

__device__ __forceinline__ uint32_t pack_bf2(__nv_bfloat16 a, __nv_bfloat16 b) {
    return (uint32_t)__bfloat16_as_ushort(a) | ((uint32_t)__bfloat16_as_ushort(b) << 16);
}
__device__ __forceinline__ float2 unpack_bf2(uint32_t u) {
    __nv_bfloat162 b = *reinterpret_cast<__nv_bfloat162*>(&u);
    return make_float2(__bfloat162float(b.x), __bfloat162float(b.y));
}
__device__ __forceinline__ void split2(float a, float b, uint32_t& hi, uint32_t& lo) {
    __nv_bfloat16 ah = __float2bfloat16(a), bh = __float2bfloat16(b);
    __nv_bfloat16 al = __float2bfloat16(a - __bfloat162float(ah));
    __nv_bfloat16 bl = __float2bfloat16(b - __bfloat162float(bh));
    hi = pack_bf2(ah, bh);
    lo = pack_bf2(al, bl);
}

// split-bf16 GEMM: warp tile 16 rows x 64 cols, K=128
__device__ __forceinline__ void gemm16(uint32_t smu,
                                       uint32_t offA_hi, uint32_t offA_lo,
                                       int rbase, int ncol0, int lane,
                                       float (&acc)[8][4], bool zero_init) {
    if (zero_init) {
#pragma unroll
        for (int i = 0; i < 8; i++)
#pragma unroll
            for (int j = 0; j < 4; j++) acc[i][j] = 0.f;
    }
    const int arow   = rbase + (lane & 15);
    const int akoff  = (lane >> 4) * 16;
    const int bn_off = ((lane >> 4) << 3) + (lane & 7);
    const int bkoff  = ((lane >> 3) & 1) * 16;
#pragma unroll
    for (int kc = 0; kc < 8; kc++) {
        uint32_t ah[4], al[4];
        ldsm4(ah, smu + offA_hi + swoff(arow, kc * 32 + akoff));
        ldsm4(al, smu + offA_lo + swoff(arow, kc * 32 + akoff));
#pragma unroll
        for (int jp = 0; jp < 4; jp++) {
            int n = ncol0 + jp * 16 + bn_off;
            uint32_t bh[4], bl[4];
            ldsm4(bh, smu + OFF_B_HI + swoff(n, kc * 32 + bkoff));
            ldsm4(bl, smu + OFF_B_LO + swoff(n, kc * 32 + bkoff));
            mma16816(acc[2 * jp],     ah, &bh[0]);
            mma16816(acc[2 * jp],     ah, &bl[0]);
            mma16816(acc[2 * jp],     al, &bh[0]);
            mma16816(acc[2 * jp + 1], ah, &bh[2]);
            mma16816(acc[2 * jp + 1], ah, &bl[2]);
            mma16816(acc[2 * jp + 1], al, &bh[2]);
        }
    }
}

// gate GEMM: warp tile 16 rows x 32 cols, K=128, accumulate
__device__ __forceinline__ void gate16(uint32_t smu,
                                       uint32_t offA_hi, uint32_t offA_lo,
                                       int rbase, int nbase, int lane,
                                       float (&acc)[4][4]) {
    const int arow   = rbase + (lane & 15);
    const int akoff  = (lane >> 4) * 16;
    const int bn_off = ((lane >> 4) << 3) + (lane & 7);
    const int bkoff  = ((lane >> 3) & 1) * 16;
#pragma unroll
    for (int kc = 0; kc < 8; kc++) {
        uint32_t ah[4], al[4];
        ldsm4(ah, smu + offA_hi + swoff(arow, kc * 32 + akoff));
        ldsm4(al, smu + offA_lo + swoff(arow, kc * 32 + akoff));
#pragma unroll
        for (int jp = 0; jp < 2; jp++) {
            int n = nbase + jp * 16 + bn_off;
            uint32_t bh[4], bl[4];
            ldsm4(bh, smu + OFF_B_HI + swoff(n, kc * 32 + bkoff));
            ldsm4(bl, smu + OFF_B_LO + swoff(n, kc * 32 + bkoff));
            mma16816(acc[2 * jp],     ah, &bh[0]);
            mma16816(acc[2 * jp],     ah, &bl[0]);
            mma16816(acc[2 * jp],     al, &bh[0]);
            mma16816(acc[2 * jp + 1], ah, &bh[2]);
            mma16816(acc[2 * jp + 1], ah, &bl[2]);
            mma16816(acc[2 * jp + 1], al, &bh[2]);
        }
    }
}

__device__ __forceinline__ void load_B(char* smem,
                                       const __nv_bfloat16* __restrict__ gh,
                                       const __nv_bfloat16* __restrict__ gl, int tid) {
    for (int i = tid; i < 2048; i += NTHREADS) {
        int r = i >> 4, c = i & 15;
        uint32_t d = r * 256 + (((c ^ (r & 7))) << 4);
        *(uint4*)(smem + OFF_B_HI + d) = *(const uint4*)(gh + r * 128 + c * 8);
        *(uint4*)(smem + OFF_B_LO + d) = *(const uint4*)(gl + r * 128 + c * 8);
    }
}

// ---------------- weight prep ----------------
__global__ void prep_T(const float* __restrict__ Wh1, const float* __restrict__ Wu1) {
    int m = blockIdx.x, o = threadIdx.x;
    float acc = 0.f;
#pragma unroll 8
    for (int h = 0; h < S; h++)
        acc = fmaf(__ldg(&Wh1[m * S + h]), __ldg(&Wu1[h * S + o]), acc);
    g_T[m * S + o] = acc;
}

__global__ void prep_C(const float* __restrict__ W1) {
    int m = blockIdx.x, n = threadIdx.x;
    float acc = 0.f;
#pragma unroll 8
    for (int o = 0; o < S; o++)
        acc = fmaf(g_T[m * S + o], __ldg(&W1[o * MO + n]), acc);
    g_C[m * MO + n] = acc * 0.08838834764831845f;  // 1/sqrt(128)
}

__global__ void pack_w(const float* __restrict__ Wh0, const float* __restrict__ Wu0,
                       const float* __restrict__ Wm0) {
    int i = blockIdx.x * 256 + threadIdx.x;   // 98304 total
    float v;
    __nv_bfloat16 *dh, *dl;
    int pos;
    if (i < 16384) {
        int n = i >> 7, k = i & 127;
        v = Wh0[k * S + n]; dh = gWhT_hi; dl = gWhT_lo; pos = i;
    } else if (i < 32768) {
        int j = i - 16384; int n = j >> 7, k = j & 127;
        v = Wu0[k * S + n]; dh = gWuT_hi; dl = gWuT_lo; pos = j;
    } else if (i < 65536) {
        int j = i - 32768; int half = j >> 14, n = (j >> 7) & 127, k = j & 127;
        v = Wm0[(half * S + k) * S + n]; dh = gWmT_hi; dl = gWmT_lo; pos = j;
    } else {
        int j = i - 65536; int n = j >> 7, k = j & 127;
        v = g_C[k * MO + n]; dh = gCT_hi; dl = gCT_lo; pos = j;
    }
    __nv_bfloat16 h = __float2bfloat16(v);
    dh[pos] = h;
    dl[pos] = __float2bfloat16(v - __bfloat162float(h));
}

// ---------------- the fused kernel ----------------
__global__ void __launch_bounds__(NTHREADS, 1) fused(
    const float* __restrict__ x,
    const float* __restrict__ bm0,
    float* __restrict__ out)
{
    extern __shared__ char smem[];
    const uint32_t smu = (uint32_t)__cvta_generic_to_shared(smem);
    const int tid  = threadIdx.x;
    const int wid  = tid >> 5;
    const int lane = tid & 31;
    const int row0 = blockIdx.x * XR;
    float* gptr = (float*)(smem + OFF_G);
    float* stg  = (float*)(smem + OFF_STAGE);

    // ===== phase 0: pack input (vectorized) =====
    for (int p = tid; p < XR * 32; p += NTHREADS) {                // s: float4
        int row = p >> 5, c4 = (p & 31) << 2;
        float4 f = *(const float4*)(x + (size_t)(row0 + row) * 512 + c4);
        uint32_t hi, lo;
        uint32_t d = swoff(row, c4 * 2);
        split2(f.x, f.y, hi, lo);
        *(uint32_t*)(smem + OFF_S_HI + d) = hi;
        *(uint32_t*)(smem + OFF_S_LO + d) = lo;
        split2(f.z, f.w, hi, lo);
        *(uint32_t*)(smem + OFF_S_HI + d + 4) = hi;
        *(uint32_t*)(smem + OFF_S_LO + d + 4) = lo;
    }
    for (int q = tid; q < XR * 96; q += NTHREADS) {                // v: float4
        int xr = q / 96, f4 = q - xr * 96;
        float4 f = *(const float4*)(x + (size_t)(row0 + xr) * 512 + 128 + f4 * 4);
        float vals[4] = {f.x, f.y, f.z, f.w};
#pragma unroll
        for (int e = 0; e < 4; e++) {
            int j = f4 * 4 + e;
            int m = (j * 21846) >> 16;   // j/3
            int t = j - 3 * m;
            __nv_bfloat16 h = __float2bfloat16(vals[e]);
            __nv_bfloat16 l = __float2bfloat16(vals[e] - __bfloat162float(h));
            uint32_t d = swoff(t * 64 + xr, m * 2);
            *(uint16_t*)(smem + OFF_A_HI + d) = __bfloat16_as_ushort(h);
            *(uint16_t*)(smem + OFF_A_LO + d) = __bfloat16_as_ushort(l);
        }
    }
    load_B(smem, gWhT_hi, gWhT_lo, tid);
    __syncthreads();

    float acc[8][4];
    const int rbase = (wid >> 1) * 16;      // 0..184
    const int ncol0 = (wid & 1) * 64;
    const int tcomp = wid >> 3;             // t component of this warp's rows
    const int r0 = rbase + (lane >> 2), r1 = r0 + 8;
    const int xr0 = r0 & 63, xr1 = r1 & 63;

    // ===== phase 1: Vh = v @ Wh0 =====
    gemm16(smu, OFF_A_HI, OFF_A_LO, rbase, ncol0, lane, acc, true);
    __syncthreads();                        // all A/B reads done
#pragma unroll
    for (int i = 0; i < 8; i++) {
        int c = ncol0 + i * 8 + (lane & 3) * 2;
        uint32_t hi, lo;
        split2(acc[i][0], acc[i][1], hi, lo);
        uint32_t d0 = swoff(r0, c * 2);
        *(uint32_t*)(smem + OFF_A_HI + d0) = hi;
        *(uint32_t*)(smem + OFF_A_LO + d0) = lo;
        split2(acc[i][2], acc[i][3], hi, lo);
        uint32_t d1 = swoff(r1, c * 2);
        *(uint32_t*)(smem + OFF_A_HI + d1) = hi;
        *(uint32_t*)(smem + OFF_A_LO + d1) = lo;
    }
    load_B(smem, gWmT_hi, gWmT_lo, tid);    // Wm half 0
    __syncthreads();

    // ===== phase 2: vn = sqrt(sum_t Vh^2 + eps) =====
    for (int p = tid; p < XR * 64; p += NTHREADS) {
        int xr = p >> 6, h2 = (p & 63) << 1;
        float s0 = 1e-8f, s1 = 1e-8f;
#pragma unroll
        for (int t = 0; t < 3; t++) {
            uint32_t d = swoff(t * 64 + xr, h2 * 2);
            float2 fh = unpack_bf2(*(uint32_t*)(smem + OFF_A_HI + d));
            float2 fl = unpack_bf2(*(uint32_t*)(smem + OFF_A_LO + d));
            float x0 = fh.x + fl.x, x1 = fh.y + fl.y;
            s0 = fmaf(x0, x0, s0);
            s1 = fmaf(x1, x1, s1);
        }
        uint32_t hi, lo; split2(sqrtf(s0), sqrtf(s1), hi, lo);
        uint32_t d = swoff(xr, h2 * 2);
        *(uint32_t*)(smem + OFF_VN_HI + d) = hi;
        *(uint32_t*)(smem + OFF_VN_LO + d) = lo;
    }
    __syncthreads();

    // ===== phase 3: gate = sigmoid([s,vn] @ Wm0 + bm0)  (warps 0-15, 16x32 tiles) =====
    float acc2[4][4];
#pragma unroll
    for (int i = 0; i < 4; i++)
#pragma unroll
        for (int j = 0; j < 4; j++) acc2[i][j] = 0.f;
    const int grb = (wid & 3) * 16;
    const int gnb = ((wid >> 2) & 3) * 32;
    if (wid < 16)
        gate16(smu, OFF_S_HI, OFF_S_LO, grb, gnb, lane, acc2);
    __syncthreads();
    load_B(smem, gWmT_hi + 16384, gWmT_lo + 16384, tid);   // Wm half 1
    __syncthreads();
    if (wid < 16)
        gate16(smu, OFF_VN_HI, OFF_VN_LO, grb, gnb, lane, acc2);
    __syncthreads();                        // s-region reads long done; safe to write g
    if (wid < 16) {
        int gr0 = grb + (lane >> 2), gr1 = gr0 + 8;
#pragma unroll
        for (int i = 0; i < 4; i++) {
            int n = gnb + i * 8 + (lane & 3) * 2;
            float b0 = __ldg(&bm0[n]), b1 = __ldg(&bm0[n + 1]);
            gptr[gswz(gr0, n)]     = 1.f / (1.f + __expf(-(acc2[i][0] + b0)));
            gptr[gswz(gr0, n + 1)] = 1.f / (1.f + __expf(-(acc2[i][1] + b1)));
            gptr[gswz(gr1, n)]     = 1.f / (1.f + __expf(-(acc2[i][2] + b0)));
            gptr[gswz(gr1, n + 1)] = 1.f / (1.f + __expf(-(acc2[i][3] + b1)));
        }
    }
    load_B(smem, gWuT_hi, gWuT_lo, tid);
    __syncthreads();

    // ===== phase 4: v1 = (Vh @ Wu0) * g =====
    gemm16(smu, OFF_A_HI, OFF_A_LO, rbase, ncol0, lane, acc, true);
    __syncthreads();
#pragma unroll
    for (int i = 0; i < 8; i++) {
        int c = ncol0 + i * 8 + (lane & 3) * 2;
        float g00 = gptr[gswz(xr0, c)], g01 = gptr[gswz(xr0, c + 1)];
        float g10 = gptr[gswz(xr1, c)], g11 = gptr[gswz(xr1, c + 1)];
        uint32_t hi, lo;
        split2(acc[i][0] * g00, acc[i][1] * g01, hi, lo);
        uint32_t d0 = swoff(r0, c * 2);
        *(uint32_t*)(smem + OFF_A_HI + d0) = hi;
        *(uint32_t*)(smem + OFF_A_LO + d0) = lo;
        split2(acc[i][2] * g10, acc[i][3] * g11, hi, lo);
        uint32_t d1 = swoff(r1, c * 2);
        *(uint32_t*)(smem + OFF_A_HI + d1) = hi;
        *(uint32_t*)(smem + OFF_A_LO + d1) = lo;
    }
    load_B(smem, gCT_hi, gCT_lo, tid);      // C half 0
    __syncthreads();

    // ===== phase 5: vo = v1 @ C (two N-halves), staged coalesced output =====
    const int myslice = (rbase >> 4) & 3;   // 16-row slice of xr this warp owns
#pragma unroll 1
    for (int nh = 0; nh < 2; nh++) {
        gemm16(smu, OFF_A_HI, OFF_A_LO, rbase, ncol0, lane, acc, true);
#pragma unroll 1
        for (int slice = 0; slice < 4; slice++) {
            __syncthreads();                // staging free / previous flush done
            if (myslice == slice) {
                int rl0 = lane >> 2, rl1 = rl0 + 8;     // r&15
#pragma unroll
                for (int i = 0; i < 8; i++) {
                    int c  = ncol0 + i * 8 + (lane & 3) * 2;
                    int fl = c >> 4, nl = c & 15;
                    int p0 = fl * 64 + 16 + nl * 3 + tcomp;
                    int p1 = fl * 64 + 16 + (nl + 1) * 3 + tcomp;
                    stg[rl0 * 512 + (p0 ^ ((rl0 & 7) << 2))] = acc[i][0];
                    stg[rl0 * 512 + (p1 ^ ((rl0 & 7) << 2))] = acc[i][1];
                    stg[rl1 * 512 + (p0 ^ ((rl1 & 7) << 2))] = acc[i][2];
                    stg[rl1 * 512 + (p1 ^ ((rl1 & 7) << 2))] = acc[i][3];
                }
            }
            __syncthreads();
            for (int i = tid; i < 2048; i += NTHREADS) {
                int xl = i >> 7, posq = (i & 127) << 2;
                float4 v;
                if ((posq & 63) < 16) v = make_float4(0.f, 0.f, 0.f, 0.f);  // scalar: exact cancel
                else                  v = *(float4*)&stg[xl * 512 + (posq ^ ((xl & 7) << 2))];
                *(float4*)&out[(size_t)(row0 + slice * 16 + xl) * 1024 + nh * 512 + posq] = v;
            }
        }
        if (nh == 0) {
            __syncthreads();
            load_B(smem, gCT_hi + 128 * 128, gCT_lo + 128 * 128, tid);  // C half 1
            __syncthreads();
        }
    }
}

// ---------------- launch ----------------
extern "C" void kernel_launch(void* const* d_in, const int* in_sizes, int n_in,
                              void* d_out, int out_size) {
    const float* x   = (const float*)d_in[0];
    const float* Wh0 = (const float*)d_in[1];
    const float* Wu0 = (const float*)d_in[2];
    const float* Wm0 = (const float*)d_in[3];
    const float* bm0 = (const float*)d_in[4];
    const float* Wh1 = (const float*)d_in[5];
    const float* Wu1 = (const float*)d_in[6];
    // d_in[7]=Wm1, d_in[8]=bm1, d_in[9]=W0 provably unused (scalar channel cancels)
    const float* W1  = (const float*)d_in[10];
    float* out = (float*)d_out;

    cudaFuncSetAttribute(fused, cudaFuncAttributeMaxDynamicSharedMemorySize, SMEM_BYTES);

    prep_T<<<S, S>>>(Wh1, Wu1);
    prep_C<<<S, MO>>>(W1);
    pack_w<<<384, 256>>>(Wh0, Wu0, Wm0);
    fused<<<NROWS / XR, NTHREADS, SMEM_BYTES>>>(x, bm0, out);
}

// round 6
// speedup vs baseline: 2.3489x; 1.0001x over previous
#include <cuda_runtime.h>
#include <cuda_bf16.h>
#include <stdint.h>

#define S        128
#define MO       256
#define NROWS    32768       // 2048*16
#define XR       64          // x-rows per CTA
#define NTHREADS 768         // 24 warps

// ---------------- smem layout (bytes) ----------------
#define OFF_A_HI  0          // A: 192 rows x 256B (swizzled), hi
#define OFF_A_LO  49152
#define OFF_B_HI  98304      // B: 128 rows x 256B, hi
#define OFF_B_LO  131072
#define OFF_S_HI  163840     // s tile 64x256B hi
#define OFF_S_LO  180224
#define OFF_G     163840     // gate fp32 64x128 (overlaps S after s consumed)
#define OFF_VN_HI 196608     // vn tile hi
#define OFF_VN_LO 212992
#define OFF_STAGE 196608     // output staging 16x512 f32 (overlaps VN)
#define SMEM_BYTES 229376

// ---------------- weight scratch ----------------
__device__ float g_T[S * S];
__device__ float g_C[S * MO];
__device__ __nv_bfloat16 gWhT_hi[S * S],     gWhT_lo[S * S];      // [n][k]
__device__ __nv_bfloat16 gWuT_hi[S * S],     gWuT_lo[S * S];
__device__ __nv_bfloat16 gWmT_hi[2 * S * S], gWmT_lo[2 * S * S];  // [half][n][k]
__device__ __nv_bfloat16 gCT_hi[MO * S],     gCT_lo[MO * S];      // [n][k]

// ---------------- helpers ----------------
__device__ __forceinline__ uint32_t swoff(int row, int kbyte) {
    return (uint32_t)(row * 256 + ((((kbyte >> 4) ^ (row & 7)) << 4) | (kbyte & 15)));
}
// gate buffer: conflict-free row swizzle (xor multiple-of-4 keeps col pairs)
__device__ __forceinline__ uint32_t gswz(int r, int c) {
    return (uint32_t)(r * 128 + (c ^ ((r & 7) << 2)));
}

__device__ __forceinline__ void ldsm4(uint32_t* r, uint32_t addr) {
    asm volatile("ldmatrix.sync.aligned.m8n8.x4.shared.b16 {%0,%1,%2,%3}, [%4];"
                 : "=r"(r[0]), "=r"(r[1]), "=r"(r[2]), "=r"(r[3]) : "r"(addr));
}

__device__ __forceinline__ void mma16816(float (&d)[4], const uint32_t* a, const uint32_t* b) {
    asm volatile(
        "mma.sync.aligned.m16n8k16.row.col.f32.bf16.bf16.f32 "
        "{%0,%1,%2,%3},{%4,%5,%6,%7},{%8,%9},{%0,%1,%2,%3};"
        : "+f"(d[0]), "+f"(d[1]), "+f"(d[2]), "+f"(d[3])
        : "r"(a[0]), "r"(a[1]), "r"(a[2]), "r"(a[3]), "r"(b[0]), "r"(b[1]));
}

__device__ __forceinline__ uint32_t pack_bf2(__nv_bfloat16 a, __nv_bfloat16 b) {
    return (uint32_t)__bfloat16_as_ushort(a) | ((uint32_t)__bfloat16_as_ushort(b) << 16);
}
__device__ __forceinline__ float2 unpack_bf2(uint32_t u) {
    __nv_bfloat162 b = *reinterpret_cast<__nv_bfloat162*>(&u);
    return make_float2(__bfloat162float(b.x), __bfloat162float(b.y));
}
__device__ __forceinline__ void split2(float a, float b, uint32_t& hi, uint32_t& lo) {
    __nv_bfloat16 ah = __float2bfloat16(a), bh = __float2bfloat16(b);
    __nv_bfloat16 al = __float2bfloat16(a - __bfloat162float(ah));
    __nv_bfloat16 bl = __float2bfloat16(b - __bfloat162float(bh));
    hi = pack_bf2(ah, bh);
    lo = pack_bf2(al, bl);
}

// split-bf16 GEMM: warp tile 16 rows x 64 cols, K=128
__device__ __forceinline__ void gemm16(uint32_t smu,
                                       uint32_t offA_hi, uint32_t offA_lo,
                                       int rbase, int ncol0, int lane,
                                       float (&acc)[8][4], bool zero_init) {
    if (zero_init) {
#pragma unroll
        for (int i = 0; i < 8; i++)
#pragma unroll
            for (int j = 0; j < 4; j++) acc[i][j] = 0.f;
    }
    const int arow   = rbase + (lane & 15);
    const int akoff  = (lane >> 4) * 16;
    const int bn_off = ((lane >> 4) << 3) + (lane & 7);
    const int bkoff  = ((lane >> 3) & 1) * 16;
#pragma unroll
    for (int kc = 0; kc < 8; kc++) {
        uint32_t ah[4], al[4];
        ldsm4(ah, smu + offA_hi + swoff(arow, kc * 32 + akoff));
        ldsm4(al, smu + offA_lo + swoff(arow, kc * 32 + akoff));
#pragma unroll
        for (int jp = 0; jp < 4; jp++) {
            int n = ncol0 + jp * 16 + bn_off;
            uint32_t bh[4], bl[4];
            ldsm4(bh, smu + OFF_B_HI + swoff(n, kc * 32 + bkoff));
            ldsm4(bl, smu + OFF_B_LO + swoff(n, kc * 32 + bkoff));
            mma16816(acc[2 * jp],     ah, &bh[0]);
            mma16816(acc[2 * jp],     ah, &bl[0]);
            mma16816(acc[2 * jp],     al, &bh[0]);
            mma16816(acc[2 * jp + 1], ah, &bh[2]);
            mma16816(acc[2 * jp + 1], ah, &bl[2]);
            mma16816(acc[2 * jp + 1], al, &bh[2]);
        }
    }
}

// gate GEMM: warp tile 16 rows x 32 cols, K=128, accumulate
__device__ __forceinline__ void gate16(uint32_t smu,
                                       uint32_t offA_hi, uint32_t offA_lo,
                                       int rbase, int nbase, int lane,
                                       float (&acc)[4][4]) {
    const int arow   = rbase + (lane & 15);
    const int akoff  = (lane >> 4) * 16;
    const int bn_off = ((lane >> 4) << 3) + (lane & 7);
    const int bkoff  = ((lane >> 3) & 1) * 16;
#pragma unroll
    for (int kc = 0; kc < 8; kc++) {
        uint32_t ah[4], al[4];
        ldsm4(ah, smu + offA_hi + swoff(arow, kc * 32 + akoff));
        ldsm4(al, smu + offA_lo + swoff(arow, kc * 32 + akoff));
#pragma unroll
        for (int jp = 0; jp < 2; jp++) {
            int n = nbase + jp * 16 + bn_off;
            uint32_t bh[4], bl[4];
            ldsm4(bh, smu + OFF_B_HI + swoff(n, kc * 32 + bkoff));
            ldsm4(bl, smu + OFF_B_LO + swoff(n, kc * 32 + bkoff));
            mma16816(acc[2 * jp],     ah, &bh[0]);
            mma16816(acc[2 * jp],     ah, &bl[0]);
            mma16816(acc[2 * jp],     al, &bh[0]);
            mma16816(acc[2 * jp + 1], ah, &bh[2]);
            mma16816(acc[2 * jp + 1], ah, &bl[2]);
            mma16816(acc[2 * jp + 1], al, &bh[2]);
        }
    }
}

__device__ __forceinline__ void load_B(char* smem,
                                       const __nv_bfloat16* __restrict__ gh,
                                       const __nv_bfloat16* __restrict__ gl, int tid) {
    for (int i = tid; i < 2048; i += NTHREADS) {
        int r = i >> 4, c = i & 15;
        uint32_t d = r * 256 + (((c ^ (r & 7))) << 4);
        *(uint4*)(smem + OFF_B_HI + d) = *(const uint4*)(gh + r * 128 + c * 8);
        *(uint4*)(smem + OFF_B_LO + d) = *(const uint4*)(gl + r * 128 + c * 8);
    }
}

// ---------------- weight prep ----------------
__global__ void prep_T(const float* __restrict__ Wh1, const float* __restrict__ Wu1) {
    int m = blockIdx.x, o = threadIdx.x;
    float acc = 0.f;
#pragma unroll 8
    for (int h = 0; h < S; h++)
        acc = fmaf(__ldg(&Wh1[m * S + h]), __ldg(&Wu1[h * S + o]), acc);
    g_T[m * S + o] = acc;
}

__global__ void prep_C(const float* __restrict__ W1) {
    int m = blockIdx.x, n = threadIdx.x;
    float acc = 0.f;
#pragma unroll 8
    for (int o = 0; o < S; o++)
        acc = fmaf(g_T[m * S + o], __ldg(&W1[o * MO + n]), acc);
    g_C[m * MO + n] = acc * 0.08838834764831845f;  // 1/sqrt(128)
}

__global__ void pack_w(const float* __restrict__ Wh0, const float* __restrict__ Wu0,
                       const float* __restrict__ Wm0) {
    int i = blockIdx.x * 256 + threadIdx.x;   // 98304 total
    float v;
    __nv_bfloat16 *dh, *dl;
    int pos;
    if (i < 16384) {
        int n = i >> 7, k = i & 127;
        v = Wh0[k * S + n]; dh = gWhT_hi; dl = gWhT_lo; pos = i;
    } else if (i < 32768) {
        int j = i - 16384; int n = j >> 7, k = j & 127;
        v = Wu0[k * S + n]; dh = gWuT_hi; dl = gWuT_lo; pos = j;
    } else if (i < 65536) {
        int j = i - 32768; int half = j >> 14, n = (j >> 7) & 127, k = j & 127;
        v = Wm0[(half * S + k) * S + n]; dh = gWmT_hi; dl = gWmT_lo; pos = j;
    } else {
        int j = i - 65536; int n = j >> 7, k = j & 127;
        v = g_C[k * MO + n]; dh = gCT_hi; dl = gCT_lo; pos = j;
    }
    __nv_bfloat16 h = __float2bfloat16(v);
    dh[pos] = h;
    dl[pos] = __float2bfloat16(v - __bfloat162float(h));
}

// ---------------- the fused kernel ----------------
__global__ void __launch_bounds__(NTHREADS, 1) fused(
    const float* __restrict__ x,
    const float* __restrict__ bm0,
    float* __restrict__ out)
{
    extern __shared__ char smem[];
    const uint32_t smu = (uint32_t)__cvta_generic_to_shared(smem);
    const int tid  = threadIdx.x;
    const int wid  = tid >> 5;
    const int lane = tid & 31;
    const int row0 = blockIdx.x * XR;
    float* gptr = (float*)(smem + OFF_G);
    float* stg  = (float*)(smem + OFF_STAGE);

    // ===== phase 0: pack input (vectorized) =====
    for (int p = tid; p < XR * 32; p += NTHREADS) {                // s: float4
        int row = p >> 5, c4 = (p & 31) << 2;
        float4 f = *(const float4*)(x + (size_t)(row0 + row) * 512 + c4);
        uint32_t hi, lo;
        uint32_t d = swoff(row, c4 * 2);
        split2(f.x, f.y, hi, lo);
        *(uint32_t*)(smem + OFF_S_HI + d) = hi;
        *(uint32_t*)(smem + OFF_S_LO + d) = lo;
        split2(f.z, f.w, hi, lo);
        *(uint32_t*)(smem + OFF_S_HI + d + 4) = hi;
        *(uint32_t*)(smem + OFF_S_LO + d + 4) = lo;
    }
    for (int q = tid; q < XR * 96; q += NTHREADS) {                // v: float4
        int xr = q / 96, f4 = q - xr * 96;
        float4 f = *(const float4*)(x + (size_t)(row0 + xr) * 512 + 128 + f4 * 4);
        float vals[4] = {f.x, f.y, f.z, f.w};
#pragma unroll
        for (int e = 0; e < 4; e++) {
            int j = f4 * 4 + e;
            int m = (j * 21846) >> 16;   // j/3
            int t = j - 3 * m;
            __nv_bfloat16 h = __float2bfloat16(vals[e]);
            __nv_bfloat16 l = __float2bfloat16(vals[e] - __bfloat162float(h));
            uint32_t d = swoff(t * 64 + xr, m * 2);
            *(uint16_t*)(smem + OFF_A_HI + d) = __bfloat16_as_ushort(h);
            *(uint16_t*)(smem + OFF_A_LO + d) = __bfloat16_as_ushort(l);
        }
    }
    load_B(smem, gWhT_hi, gWhT_lo, tid);
    __syncthreads();

    float acc[8][4];
    const int rbase = (wid >> 1) * 16;      // 0..184
    const int ncol0 = (wid & 1) * 64;
    const int tcomp = wid >> 3;             // t component of this warp's rows
    const int r0 = rbase + (lane >> 2), r1 = r0 + 8;
    const int xr0 = r0 & 63, xr1 = r1 & 63;

    // ===== phase 1: Vh = v @ Wh0 =====
    gemm16(smu, OFF_A_HI, OFF_A_LO, rbase, ncol0, lane, acc, true);
    __syncthreads();                        // all A/B reads done
#pragma unroll
    for (int i = 0; i < 8; i++) {
        int c = ncol0 + i * 8 + (lane & 3) * 2;
        uint32_t hi, lo;
        split2(acc[i][0], acc[i][1], hi, lo);
        uint32_t d0 = swoff(r0, c * 2);
        *(uint32_t*)(smem + OFF_A_HI + d0) = hi;
        *(uint32_t*)(smem + OFF_A_LO + d0) = lo;
        split2(acc[i][2], acc[i][3], hi, lo);
        uint32_t d1 = swoff(r1, c * 2);
        *(uint32_t*)(smem + OFF_A_HI + d1) = hi;
        *(uint32_t*)(smem + OFF_A_LO + d1) = lo;
    }
    load_B(smem, gWmT_hi, gWmT_lo, tid);    // Wm half 0
    __syncthreads();

    // ===== phase 2: vn = sqrt(sum_t Vh^2 + eps) =====
    for (int p = tid; p < XR * 64; p += NTHREADS) {
        int xr = p >> 6, h2 = (p & 63) << 1;
        float s0 = 1e-8f, s1 = 1e-8f;
#pragma unroll
        for (int t = 0; t < 3; t++) {
            uint32_t d = swoff(t * 64 + xr, h2 * 2);
            float2 fh = unpack_bf2(*(uint32_t*)(smem + OFF_A_HI + d));
            float2 fl = unpack_bf2(*(uint32_t*)(smem + OFF_A_LO + d));
            float x0 = fh.x + fl.x, x1 = fh.y + fl.y;
            s0 = fmaf(x0, x0, s0);
            s1 = fmaf(x1, x1, s1);
        }
        uint32_t hi, lo; split2(sqrtf(s0), sqrtf(s1), hi, lo);
        uint32_t d = swoff(xr, h2 * 2);
        *(uint32_t*)(smem + OFF_VN_HI + d) = hi;
        *(uint32_t*)(smem + OFF_VN_LO + d) = lo;
    }
    __syncthreads();

    // ===== phase 3: gate = sigmoid([s,vn] @ Wm0 + bm0)  (warps 0-15, 16x32 tiles) =====
    float acc2[4][4];
#pragma unroll
    for (int i = 0; i < 4; i++)
#pragma unroll
        for (int j = 0; j < 4; j++) acc2[i][j] = 0.f;
    const int grb = (wid & 3) * 16;
    const int gnb = ((wid >> 2) & 3) * 32;
    if (wid < 16)
        gate16(smu, OFF_S_HI, OFF_S_LO, grb, gnb, lane, acc2);
    __syncthreads();
    load_B(smem, gWmT_hi + 16384, gWmT_lo + 16384, tid);   // Wm half 1
    __syncthreads();
    if (wid < 16)
        gate16(smu, OFF_VN_HI, OFF_VN_LO, grb, gnb, lane, acc2);
    __syncthreads();                        // s-region reads long done; safe to write g
    if (wid < 16) {
        int gr0 = grb + (lane >> 2), gr1 = gr0 + 8;
#pragma unroll
        for (int i = 0; i < 4; i++) {
            int n = gnb + i * 8 + (lane & 3) * 2;
            float b0 = __ldg(&bm0[n]), b1 = __ldg(&bm0[n + 1]);
            gptr[gswz(gr0, n)]     = 1.f / (1.f + __expf(-(acc2[i][0] + b0)));
            gptr[gswz(gr0, n + 1)] = 1.f / (1.f + __expf(-(acc2[i][1] + b1)));
            gptr[gswz(gr1, n)]     = 1.f / (1.f + __expf(-(acc2[i][2] + b0)));
            gptr[gswz(gr1, n + 1)] = 1.f / (1.f + __expf(-(acc2[i][3] + b1)));
        }
    }
    load_B(smem, gWuT_hi, gWuT_lo, tid);
    __syncthreads();

    // ===== phase 4: v1 = (Vh @ Wu0) * g =====
    gemm16(smu, OFF_A_HI, OFF_A_LO, rbase, ncol0, lane, acc, true);
    __syncthreads();
#pragma unroll
    for (int i = 0; i < 8; i++) {
        int c = ncol0 + i * 8 + (lane & 3) * 2;
        float g00 = gptr[gswz(xr0, c)], g01 = gptr[gswz(xr0, c + 1)];
        float g10 = gptr[gswz(xr1, c)], g11 = gptr[gswz(xr1, c + 1)];
        uint32_t hi, lo;
        split2(acc[i][0] * g00, acc[i][1] * g01, hi, lo);
        uint32_t d0 = swoff(r0, c * 2);
        *(uint32_t*)(smem + OFF_A_HI + d0) = hi;
        *(uint32_t*)(smem + OFF_A_LO + d0) = lo;
        split2(acc[i][2] * g10, acc[i][3] * g11, hi, lo);
        uint32_t d1 = swoff(r1, c * 2);
        *(uint32_t*)(smem + OFF_A_HI + d1) = hi;
        *(uint32_t*)(smem + OFF_A_LO + d1) = lo;
    }
    load_B(smem, gCT_hi, gCT_lo, tid);      // C half 0
    __syncthreads();

    // ===== phase 5: vo = v1 @ C (two N-halves), staged coalesced output =====
    const int myslice = (rbase >> 4) & 3;   // 16-row slice of xr this warp owns
#pragma unroll 1
    for (int nh = 0; nh < 2; nh++) {
        gemm16(smu, OFF_A_HI, OFF_A_LO, rbase, ncol0, lane, acc, true);
#pragma unroll 1
        for (int slice = 0; slice < 4; slice++) {
            __syncthreads();                // staging free / previous flush done
            if (myslice == slice) {
                int rl0 = lane >> 2, rl1 = rl0 + 8;     // r&15
#pragma unroll
                for (int i = 0; i < 8; i++) {
                    int c  = ncol0 + i * 8 + (lane & 3) * 2;
                    int fl = c >> 4, nl = c & 15;
                    int p0 = fl * 64 + 16 + nl * 3 + tcomp;
                    int p1 = fl * 64 + 16 + (nl + 1) * 3 + tcomp;
                    stg[rl0 * 512 + (p0 ^ ((rl0 & 7) << 2))] = acc[i][0];
                    stg[rl0 * 512 + (p1 ^ ((rl0 & 7) << 2))] = acc[i][1];
                    stg[rl1 * 512 + (p0 ^ ((rl1 & 7) << 2))] = acc[i][2];
                    stg[rl1 * 512 + (p1 ^ ((rl1 & 7) << 2))] = acc[i][3];
                }
            }
            __syncthreads();
            for (int i = tid; i < 2048; i += NTHREADS) {
                int xl = i >> 7, posq = (i & 127) << 2;
                float4 v;
                if ((posq & 63) < 16) v = make_float4(0.f, 0.f, 0.f, 0.f);  // scalar: exact cancel
                else                  v = *(float4*)&stg[xl * 512 + (posq ^ ((xl & 7) << 2))];
                *(float4*)&out[(size_t)(row0 + slice * 16 + xl) * 1024 + nh * 512 + posq] = v;
            }
        }
        if (nh == 0) {
            __syncthreads();
            load_B(smem, gCT_hi + 128 * 128, gCT_lo + 128 * 128, tid);  // C half 1
            __syncthreads();
        }
    }
}

// ---------------- launch ----------------
extern "C" void kernel_launch(void* const* d_in, const int* in_sizes, int n_in,
                              void* d_out, int out_size) {
    const float* x   = (const float*)d_in[0];
    const float* Wh0 = (const float*)d_in[1];
    const float* Wu0 = (const float*)d_in[2];
    const float* Wm0 = (const float*)d_in[3];
    const float* bm0 = (const float*)d_in[4];
    const float* Wh1 = (const float*)d_in[5];
    const float* Wu1 = (const float*)d_in[6];
    // d_in[7]=Wm1, d_in[8]=bm1, d_in[9]=W0 provably unused (scalar channel cancels)
    const float* W1  = (const float*)d_in[10];
    float* out = (float*)d_out;

    cudaFuncSetAttribute(fused, cudaFuncAttributeMaxDynamicSharedMemorySize, SMEM_BYTES);

    prep_T<<<S, S>>>(Wh1, Wu1);
    prep_C<<<S, MO>>>(W1);
    pack_w<<<384, 256>>>(Wh0, Wu0, Wm0);
    fused<<<NROWS / XR, NTHREADS, SMEM_BYTES>>>(x, bm0, out);
}